// round 15
// baseline (speedup 1.0000x reference)
#include <cuda_runtime.h>
#include <math.h>

#define NB 16
#define H 512
#define W 512
#define KR 15
#define MUF 5.0f
#define QS 8.0f                       // vsum quant scale
#define BOXSCALE (1.0f/(961.0f*8.0f)) // KKINV / QS
#define ROWS 16                       // rows per block
#define VSTRIDE 544                   // 16B pad | 512 cols | 16B pad
#define NBLK (NB * (H / ROWS))        // 512 blocks

__device__ float4 g_part4[NBLK];      // per-block partials
__device__ unsigned int g_count;      // zero-init; self-resetting

__global__ void __launch_bounds__(256, 7)
fused_kernel(const float* __restrict__ pred,
             const float* __restrict__ mask,
             float* __restrict__ out) {
    __shared__ unsigned char s_v[ROWS * VSTRIDE];   // u8 vsums, padded rows (8.7KB)
    __shared__ float red[32];                       // 8 warps x 4
    __shared__ float flag;

    const int t  = threadIdx.x;         // 0..255
    const int b  = blockIdx.x >> 5;     // batch
    const int r0 = (blockIdx.x & 31) * ROWS;

    const float* mb = mask + (size_t)b * H * W;
    const float* pb = pred + (size_t)(b * 2 + 1) * H * W;   // channel-1 logits

    // ---- zero smem pads: 16 rows x 8 words (4 left, 4 right) = 128 words ----
    if (t < 128) {
        const int row = t >> 3;
        const int idx = t & 7;
        const int off = row * VSTRIDE + (idx < 4 ? idx * 4 : 528 + (idx - 4) * 4);
        *(unsigned int*)&s_v[off] = 0u;
    }

    // ========== Phase A: vertical sliding box sum -> smem u8 (block-local) ==
    {
        const float2* mb2 = (const float2*)mb;
        const int c = t;                // owns cols 2c, 2c+1

        // 4-way tree init of window [r0-15, r0+15], BOTH ends clamped.
        // (R14 bug: with 8-row strips hi=r0+15 overran row 511 — OOB reads.)
        float ax[4] = {0.f, 0.f, 0.f, 0.f};
        float ay[4] = {0.f, 0.f, 0.f, 0.f};
        int lo = r0 - KR; if (lo < 0) lo = 0;
        int hi = r0 + KR; if (hi > H - 1) hi = H - 1;   // r0<=496 -> hi<=511
        int k = 0;
        for (int j = lo; j <= hi; ++j, ++k) {
            float2 v = mb2[j * (W / 2) + c];
            ax[k & 3] += v.x; ay[k & 3] += v.y;
        }
        const float ix = (ax[0] + ax[1]) + (ax[2] + ax[3]);
        const float iy = (ay[0] + ay[1]) + (ay[2] + ay[3]);

        // independent add / sub chains over 16 rows
        float addx = 0.f, addy = 0.f, subx = 0.f, suby = 0.f;
        #pragma unroll
        for (int rr = 0; rr < ROWS; ++rr) {
            const int r = r0 + rr;
            float vx = (ix + addx) - subx;
            float vy = (iy + addy) - suby;
            unsigned qx = (unsigned)__float2int_rn(vx * QS);
            unsigned qy = (unsigned)__float2int_rn(vy * QS);
            *(unsigned short*)&s_v[rr * VSTRIDE + 16 + 2 * c] =
                (unsigned short)(qx | (qy << 8));
            int ar = r + KR + 1;
            int sr = r - KR;
            if (ar < H) {
                float2 v = mb2[ar * (W / 2) + c];
                addx += v.x; addy += v.y;
            }
            if (sr >= 0) {
                float2 v = mb2[sr * (W / 2) + c];
                subx += v.x; suby += v.y;
            }
        }
    }
    __syncthreads();

    // ========== Phase B: dp4a horizontal box + elementwise ==================
    const int u = t & 63;               // thread within row (8 cols each)
    const int g = t >> 6;               // 0..3

    float a0 = 0.f, a1 = 0.f, a2 = 0.f, a3 = 0.f;

    #pragma unroll
    for (int pass = 0; pass < 4; ++pass) {
        const int lr = pass * 4 + g;    // local row 0..15
        const int r  = r0 + lr;

        // 5 aligned LDS.64 covering bytes 8u .. 8u+39 of the padded row
        const uint2* vrow = (const uint2*)&s_v[lr * VSTRIDE];
        uint2 L0 = vrow[u + 0];
        uint2 L1 = vrow[u + 1];
        uint2 L2 = vrow[u + 2];
        uint2 L3 = vrow[u + 3];
        uint2 L4 = vrow[u + 4];

        // streaming inputs: fp32 mask (L1/L2-hot from phase A) + pred (DRAM)
        const float4* mrow = (const float4*)(mb + (size_t)r * W);
        const float4* prow = (const float4*)(pb + (size_t)r * W);
        float4 m4a = mrow[u * 2 + 0];
        float4 m4b = mrow[u * 2 + 1];
        float4 p4a = __ldcg(&prow[u * 2 + 0]);
        float4 p4b = __ldcg(&prow[u * 2 + 1]);

        // integer prefix over 40 bytes via dp4a
        unsigned w0 = L0.x, w1 = L0.y, w8 = L4.x, w9 = L4.y;
        const unsigned M1 = 0x01010101u;
        unsigned wp1 = __dp4a(w0, M1, 0u);
        unsigned wp2 = __dp4a(w1, M1, wp1);
        unsigned wp3 = __dp4a(L1.x, M1, wp2);
        unsigned wp4 = __dp4a(L1.y, M1, wp3);
        unsigned wp5 = __dp4a(L2.x, M1, wp4);
        unsigned wp6 = __dp4a(L2.y, M1, wp5);
        unsigned wp7 = __dp4a(L3.x, M1, wp6);
        unsigned wp8 = __dp4a(L3.y, M1, wp7);
        unsigned wp9 = __dp4a(w8, M1, wp8);

        unsigned loS[8], hiS[8];
        loS[0] = __dp4a(w0, 0x00000001u, 0u);
        loS[1] = __dp4a(w0, 0x00000101u, 0u);
        loS[2] = __dp4a(w0, 0x00010101u, 0u);
        loS[3] = wp1;
        loS[4] = __dp4a(w1, 0x00000001u, wp1);
        loS[5] = __dp4a(w1, 0x00000101u, wp1);
        loS[6] = __dp4a(w1, 0x00010101u, wp1);
        loS[7] = wp2;
        hiS[0] = wp8;
        hiS[1] = __dp4a(w8, 0x00000001u, wp8);
        hiS[2] = __dp4a(w8, 0x00000101u, wp8);
        hiS[3] = __dp4a(w8, 0x00010101u, wp8);
        hiS[4] = wp9;
        hiS[5] = __dp4a(w9, 0x00000001u, wp9);
        hiS[6] = __dp4a(w9, 0x00000101u, wp9);
        hiS[7] = __dp4a(w9, 0x00010101u, wp9);

        float mv[8] = {m4a.x, m4a.y, m4a.z, m4a.w, m4b.x, m4b.y, m4b.z, m4b.w};
        float pv[8] = {p4a.x, p4a.y, p4a.z, p4a.w, p4b.x, p4b.y, p4b.z, p4b.w};

        #pragma unroll
        for (int i = 0; i < 8; ++i) {
            float box  = (float)(int)(hiS[i] - loS[i]) * BOXSCALE;
            float m    = mv[i];
            float p    = pv[i];
            float weit = 1.0f + MUF * fabsf(box - m);

            float eexp = __expf(-fabsf(p));
            float bce  = fmaxf(p, 0.0f) - p * m + __logf(1.0f + eexp);
            float rcp  = __fdividef(1.0f, 1.0f + eexp);
            float ps   = (p >= 0.0f) ? rcp : eexp * rcp;

            a0 += weit * bce;
            a1 += weit;
            float wps = weit * ps;
            a2 += wps * m;
            a3 += wps + weit * m;
        }
    }

    // ---- warp reduction ----
    const int wid  = t >> 5;
    const int lane = t & 31;
    #pragma unroll
    for (int d = 16; d > 0; d >>= 1) {
        a0 += __shfl_down_sync(0xffffffffu, a0, d);
        a1 += __shfl_down_sync(0xffffffffu, a1, d);
        a2 += __shfl_down_sync(0xffffffffu, a2, d);
        a3 += __shfl_down_sync(0xffffffffu, a3, d);
    }
    if (lane == 0) {
        red[wid * 4 + 0] = a0;
        red[wid * 4 + 1] = a1;
        red[wid * 4 + 2] = a2;
        red[wid * 4 + 3] = a3;
    }
    __syncthreads();

    // ---- cross-warp reduction in warp 0 (shuffle tree) ----
    if (wid == 0) {
        float y = red[lane];                 // lane = w*4 + k, w<8, k<4
        y += __shfl_xor_sync(0xffffffffu, y, 4);
        y += __shfl_xor_sync(0xffffffffu, y, 8);
        y += __shfl_xor_sync(0xffffffffu, y, 16);
        float s0 = __shfl_sync(0xffffffffu, y, 0);
        float s1 = __shfl_sync(0xffffffffu, y, 1);
        float s2 = __shfl_sync(0xffffffffu, y, 2);
        float s3 = __shfl_sync(0xffffffffu, y, 3);
        if (lane == 0) {
            __stcg(&g_part4[blockIdx.x], make_float4(s0, s1, s2, s3));
            unsigned int old;
            asm volatile("atom.acq_rel.gpu.global.add.u32 %0, [%1], %2;"
                         : "=r"(old) : "l"(&g_count), "r"(1u) : "memory");
            flag = (old == NBLK - 1) ? 1.f : 0.f;
        }
    }
    __syncthreads();

    // ---------- last block finalizes ----------
    if (flag != 0.f) {
        if (t < 128) {
            const int bb = t >> 3;           // batch 0..15
            const int j  = t & 7;            // chunk 0..7 (4 blocks each)
            float s0 = 0.f, s1 = 0.f, s2 = 0.f, s3 = 0.f;
            const float4* gp = g_part4 + bb * (NBLK / NB) + j * 4;
            #pragma unroll
            for (int kk = 0; kk < 4; ++kk) {
                float4 vv = __ldcg(&gp[kk]);
                s0 += vv.x; s1 += vv.y; s2 += vv.z; s3 += vv.w;
            }
            #pragma unroll
            for (int d = 4; d > 0; d >>= 1) {
                s0 += __shfl_down_sync(0xffffffffu, s0, d, 8);
                s1 += __shfl_down_sync(0xffffffffu, s1, d, 8);
                s2 += __shfl_down_sync(0xffffffffu, s2, d, 8);
                s3 += __shfl_down_sync(0xffffffffu, s3, d, 8);
            }
            if (j == 0) {
                float wbce = s0 / s1;
                float wiou = 1.0f - (s2 + 1.0f) / (s3 - s2 + 1.0f);
                red[bb] = wbce + wiou;
            }
        }
        __syncthreads();
        if (t == 0) {
            float s = 0.f;
            #pragma unroll
            for (int kk = 0; kk < NB; ++kk) s += red[kk];
            out[0] = s * (1.0f / NB);
            g_count = 0;                     // self-reset for next graph replay
        }
    }
}

extern "C" void kernel_launch(void* const* d_in, const int* in_sizes, int n_in,
                              void* d_out, int out_size) {
    const float* pred = (const float*)d_in[0];
    const float* mask = (const float*)d_in[1];
    if (n_in >= 2 && in_sizes[0] == NB * H * W && in_sizes[1] == NB * 2 * H * W) {
        mask = (const float*)d_in[0];
        pred = (const float*)d_in[1];
    }
    float* out = (float*)d_out;

    fused_kernel<<<NBLK, 256>>>(pred, mask, out);
}

// round 16
// speedup vs baseline: 1.0015x; 1.0015x over previous
#include <cuda_runtime.h>
#include <math.h>

#define NB 16
#define H 512
#define W 512
#define KR 15
#define MUF 5.0f
#define QS 8.0f                       // vsum quant scale
#define BOXSCALE (1.0f/(961.0f*8.0f)) // KKINV / QS
#define ROWS 8                        // rows per block
#define VSTRIDE 544                   // 16B pad | 512 cols | 16B pad
#define NBLK (NB * (H / ROWS))        // 1024 blocks

__device__ float4 g_part4[NBLK];      // per-block partials
__device__ unsigned int g_count;      // zero-init; self-resetting

__global__ void __launch_bounds__(256, 7)
fused_kernel(const float* __restrict__ pred,
             const float* __restrict__ mask,
             float* __restrict__ out) {
    __shared__ unsigned char s_v[ROWS * VSTRIDE];   // u8 vsums, padded rows (4.3KB)
    __shared__ float red[32];                       // 8 warps x 4
    __shared__ float flag;

    const int t  = threadIdx.x;         // 0..255
    const int b  = blockIdx.x >> 6;     // batch
    const int r0 = (blockIdx.x & 63) * ROWS;

    const float* mb = mask + (size_t)b * H * W;
    const float* pb = pred + (size_t)(b * 2 + 1) * H * W;   // channel-1 logits

    // ---- zero smem pads: 8 rows x 8 words (4 left, 4 right) = 64 words ----
    if (t < 64) {
        const int row = t >> 3;
        const int idx = t & 7;
        const int off = row * VSTRIDE + (idx < 4 ? idx * 4 : 528 + (idx - 4) * 4);
        *(unsigned int*)&s_v[off] = 0u;
    }

    // ========== Phase A: vertical sliding box sum -> smem u8 (block-local) ==
    {
        const float2* mb2 = (const float2*)mb;
        const int c = t;                // owns cols 2c, 2c+1

        // 4-way tree init of window [r0-15, r0+15], BOTH ends clamped.
        // (R14 bug: hi unclamped overran row 511 for r0=504 — OOB reads.)
        float ax[4] = {0.f, 0.f, 0.f, 0.f};
        float ay[4] = {0.f, 0.f, 0.f, 0.f};
        int lo = r0 - KR; if (lo < 0) lo = 0;
        int hi = r0 + KR; if (hi > H - 1) hi = H - 1;
        int k = 0;
        for (int j = lo; j <= hi; ++j, ++k) {
            float2 v = mb2[j * (W / 2) + c];
            ax[k & 3] += v.x; ay[k & 3] += v.y;
        }
        const float ix = (ax[0] + ax[1]) + (ax[2] + ax[3]);
        const float iy = (ay[0] + ay[1]) + (ay[2] + ay[3]);

        // independent add / sub chains over 8 rows (both ends guarded)
        float addx = 0.f, addy = 0.f, subx = 0.f, suby = 0.f;
        #pragma unroll
        for (int rr = 0; rr < ROWS; ++rr) {
            const int r = r0 + rr;
            float vx = (ix + addx) - subx;
            float vy = (iy + addy) - suby;
            unsigned qx = (unsigned)__float2int_rn(vx * QS);
            unsigned qy = (unsigned)__float2int_rn(vy * QS);
            *(unsigned short*)&s_v[rr * VSTRIDE + 16 + 2 * c] =
                (unsigned short)(qx | (qy << 8));
            int ar = r + KR + 1;
            int sr = r - KR;
            if (ar < H) {
                float2 v = mb2[ar * (W / 2) + c];
                addx += v.x; addy += v.y;
            }
            if (sr >= 0) {
                float2 v = mb2[sr * (W / 2) + c];
                subx += v.x; suby += v.y;
            }
        }
    }
    __syncthreads();

    // ========== Phase B: dp4a horizontal box + elementwise ==================
    const int u = t & 63;               // thread within row (8 cols each)
    const int g = t >> 6;               // 0..3

    float a0 = 0.f, a1 = 0.f, a2 = 0.f, a3 = 0.f;

    #pragma unroll
    for (int pass = 0; pass < 2; ++pass) {
        const int lr = pass * 4 + g;    // local row 0..7
        const int r  = r0 + lr;

        // 5 aligned LDS.64 covering bytes 8u .. 8u+39 of the padded row
        const uint2* vrow = (const uint2*)&s_v[lr * VSTRIDE];
        uint2 L0 = vrow[u + 0];
        uint2 L1 = vrow[u + 1];
        uint2 L2 = vrow[u + 2];
        uint2 L3 = vrow[u + 3];
        uint2 L4 = vrow[u + 4];

        // streaming inputs: fp32 mask (L1/L2-hot from phase A) + pred (DRAM)
        const float4* mrow = (const float4*)(mb + (size_t)r * W);
        const float4* prow = (const float4*)(pb + (size_t)r * W);
        float4 m4a = mrow[u * 2 + 0];
        float4 m4b = mrow[u * 2 + 1];
        float4 p4a = __ldcg(&prow[u * 2 + 0]);
        float4 p4b = __ldcg(&prow[u * 2 + 1]);

        // integer prefix over 40 bytes via dp4a
        unsigned w0 = L0.x, w1 = L0.y, w8 = L4.x, w9 = L4.y;
        const unsigned M1 = 0x01010101u;
        unsigned wp1 = __dp4a(w0, M1, 0u);
        unsigned wp2 = __dp4a(w1, M1, wp1);
        unsigned wp3 = __dp4a(L1.x, M1, wp2);
        unsigned wp4 = __dp4a(L1.y, M1, wp3);
        unsigned wp5 = __dp4a(L2.x, M1, wp4);
        unsigned wp6 = __dp4a(L2.y, M1, wp5);
        unsigned wp7 = __dp4a(L3.x, M1, wp6);
        unsigned wp8 = __dp4a(L3.y, M1, wp7);
        unsigned wp9 = __dp4a(w8, M1, wp8);

        unsigned loS[8], hiS[8];
        loS[0] = __dp4a(w0, 0x00000001u, 0u);
        loS[1] = __dp4a(w0, 0x00000101u, 0u);
        loS[2] = __dp4a(w0, 0x00010101u, 0u);
        loS[3] = wp1;
        loS[4] = __dp4a(w1, 0x00000001u, wp1);
        loS[5] = __dp4a(w1, 0x00000101u, wp1);
        loS[6] = __dp4a(w1, 0x00010101u, wp1);
        loS[7] = wp2;
        hiS[0] = wp8;
        hiS[1] = __dp4a(w8, 0x00000001u, wp8);
        hiS[2] = __dp4a(w8, 0x00000101u, wp8);
        hiS[3] = __dp4a(w8, 0x00010101u, wp8);
        hiS[4] = wp9;
        hiS[5] = __dp4a(w9, 0x00000001u, wp9);
        hiS[6] = __dp4a(w9, 0x00000101u, wp9);
        hiS[7] = __dp4a(w9, 0x00010101u, wp9);

        float mv[8] = {m4a.x, m4a.y, m4a.z, m4a.w, m4b.x, m4b.y, m4b.z, m4b.w};
        float pv[8] = {p4a.x, p4a.y, p4a.z, p4a.w, p4b.x, p4b.y, p4b.z, p4b.w};

        #pragma unroll
        for (int i = 0; i < 8; ++i) {
            float box  = (float)(int)(hiS[i] - loS[i]) * BOXSCALE;
            float m    = mv[i];
            float p    = pv[i];
            float weit = 1.0f + MUF * fabsf(box - m);

            float eexp = __expf(-fabsf(p));
            float bce  = fmaxf(p, 0.0f) - p * m + __logf(1.0f + eexp);
            float rcp  = __fdividef(1.0f, 1.0f + eexp);
            float ps   = (p >= 0.0f) ? rcp : eexp * rcp;

            a0 += weit * bce;
            a1 += weit;
            float wps = weit * ps;
            a2 += wps * m;
            a3 += wps + weit * m;
        }
    }

    // ---- warp reduction ----
    const int wid  = t >> 5;
    const int lane = t & 31;
    #pragma unroll
    for (int d = 16; d > 0; d >>= 1) {
        a0 += __shfl_down_sync(0xffffffffu, a0, d);
        a1 += __shfl_down_sync(0xffffffffu, a1, d);
        a2 += __shfl_down_sync(0xffffffffu, a2, d);
        a3 += __shfl_down_sync(0xffffffffu, a3, d);
    }
    if (lane == 0) {
        red[wid * 4 + 0] = a0;
        red[wid * 4 + 1] = a1;
        red[wid * 4 + 2] = a2;
        red[wid * 4 + 3] = a3;
    }
    __syncthreads();

    // ---- cross-warp reduction in warp 0 (shuffle tree) ----
    if (wid == 0) {
        float y = red[lane];                 // lane = w*4 + k, w<8, k<4
        y += __shfl_xor_sync(0xffffffffu, y, 4);
        y += __shfl_xor_sync(0xffffffffu, y, 8);
        y += __shfl_xor_sync(0xffffffffu, y, 16);
        float s0 = __shfl_sync(0xffffffffu, y, 0);
        float s1 = __shfl_sync(0xffffffffu, y, 1);
        float s2 = __shfl_sync(0xffffffffu, y, 2);
        float s3 = __shfl_sync(0xffffffffu, y, 3);
        if (lane == 0) {
            __stcg(&g_part4[blockIdx.x], make_float4(s0, s1, s2, s3));
            unsigned int old;
            asm volatile("atom.acq_rel.gpu.global.add.u32 %0, [%1], %2;"
                         : "=r"(old) : "l"(&g_count), "r"(1u) : "memory");
            flag = (old == NBLK - 1) ? 1.f : 0.f;
        }
    }
    __syncthreads();

    // ---------- last block finalizes ----------
    if (flag != 0.f) {
        if (t < 128) {
            const int bb = t >> 3;           // batch 0..15
            const int j  = t & 7;            // chunk 0..7 (8 blocks each)
            float s0 = 0.f, s1 = 0.f, s2 = 0.f, s3 = 0.f;
            const float4* gp = g_part4 + bb * (NBLK / NB) + j * 8;
            #pragma unroll
            for (int kk = 0; kk < 8; ++kk) {
                float4 vv = __ldcg(&gp[kk]);
                s0 += vv.x; s1 += vv.y; s2 += vv.z; s3 += vv.w;
            }
            #pragma unroll
            for (int d = 4; d > 0; d >>= 1) {
                s0 += __shfl_down_sync(0xffffffffu, s0, d, 8);
                s1 += __shfl_down_sync(0xffffffffu, s1, d, 8);
                s2 += __shfl_down_sync(0xffffffffu, s2, d, 8);
                s3 += __shfl_down_sync(0xffffffffu, s3, d, 8);
            }
            if (j == 0) {
                float wbce = s0 / s1;
                float wiou = 1.0f - (s2 + 1.0f) / (s3 - s2 + 1.0f);
                red[bb] = wbce + wiou;
            }
        }
        __syncthreads();
        if (t == 0) {
            float s = 0.f;
            #pragma unroll
            for (int kk = 0; kk < NB; ++kk) s += red[kk];
            out[0] = s * (1.0f / NB);
            g_count = 0;                     // self-reset for next graph replay
        }
    }
}

extern "C" void kernel_launch(void* const* d_in, const int* in_sizes, int n_in,
                              void* d_out, int out_size) {
    const float* pred = (const float*)d_in[0];
    const float* mask = (const float*)d_in[1];
    if (n_in >= 2 && in_sizes[0] == NB * H * W && in_sizes[1] == NB * 2 * H * W) {
        mask = (const float*)d_in[0];
        pred = (const float*)d_in[1];
    }
    float* out = (float*)d_out;

    fused_kernel<<<NBLK, 256>>>(pred, mask, out);
}

// round 17
// speedup vs baseline: 1.2448x; 1.2429x over previous
#include <cuda_runtime.h>
#include <math.h>

#define NB 16
#define H 512
#define W 512
#define KR 15
#define MUF 5.0f
#define QS 8.0f                       // vsum quant scale
#define BOXSCALE (1.0f/(961.0f*8.0f)) // KKINV / QS
#define ROWS 8                        // rows per block
#define VSTRIDE 544                   // 16B pad | 512 cols | 16B pad
#define NBLK (NB * (H / ROWS))        // 1024 blocks

__device__ float4 g_part4[NBLK];      // per-block partials
__device__ unsigned int g_count;      // zero-init; self-resetting

__global__ void __launch_bounds__(256, 7)
fused_kernel(const float* __restrict__ pred,
             const float* __restrict__ mask,
             float* __restrict__ out) {
    __shared__ unsigned char s_v[ROWS * VSTRIDE];   // u8 vsums, padded rows (4.3KB)
    __shared__ float red[32];                       // 8 warps x 4
    __shared__ float flag;

    const int t  = threadIdx.x;         // 0..255
    const int b  = blockIdx.x >> 6;     // batch
    const int r0 = (blockIdx.x & 63) * ROWS;

    const float* mb = mask + (size_t)b * H * W;
    const float* pb = pred + (size_t)(b * 2 + 1) * H * W;   // channel-1 logits

    // ---- zero smem pads: 8 rows x 8 words (4 left, 4 right) = 64 words ----
    if (t < 64) {
        const int row = t >> 3;
        const int idx = t & 7;
        const int off = row * VSTRIDE + (idx < 4 ? idx * 4 : 528 + (idx - 4) * 4);
        *(unsigned int*)&s_v[off] = 0u;
    }

    // ========== Phase A: vertical sliding box sum -> smem u8 (block-local) ==
    {
        const float2* mb2 = (const float2*)mb;
        const int c = t;                // owns cols 2c, 2c+1

        if (r0 >= 16 && r0 <= H - 24) {
            // -------- fast path (60/64 strips): no clamps anywhere --------
            // init window rows r0-15 .. r0+15; static offsets -> LDG immediates
            const float2* pw = mb2 + (size_t)(r0 - KR) * (W / 2) + c;
            float ax[4] = {0.f, 0.f, 0.f, 0.f};
            float ay[4] = {0.f, 0.f, 0.f, 0.f};
            #pragma unroll
            for (int k = 0; k < 31; ++k) {
                float2 v = pw[k * (W / 2)];
                ax[k & 3] += v.x; ay[k & 3] += v.y;
            }
            const float ix = (ax[0] + ax[1]) + (ax[2] + ax[3]);
            const float iy = (ay[0] + ay[1]) + (ay[2] + ay[3]);

            const float2* pa = pw + 31 * (W / 2);   // row r0+16
            // pw itself points at row r0-15 (first subtraction row)
            float addx = 0.f, addy = 0.f, subx = 0.f, suby = 0.f;
            #pragma unroll
            for (int rr = 0; rr < ROWS; ++rr) {
                float vx = (ix + addx) - subx;
                float vy = (iy + addy) - suby;
                unsigned qx = (unsigned)__float2int_rn(vx * QS);
                unsigned qy = (unsigned)__float2int_rn(vy * QS);
                *(unsigned short*)&s_v[rr * VSTRIDE + 16 + 2 * c] =
                    (unsigned short)(qx | (qy << 8));
                float2 va = pa[rr * (W / 2)];        // rows r0+16 .. r0+23 (<512)
                float2 vs = pw[rr * (W / 2)];        // rows r0-15 .. r0-8 (L1 hit)
                addx += va.x; addy += va.y;
                subx += vs.x; suby += vs.y;
            }
        } else {
            // -------- generic path (boundary strips): both ends clamped ----
            float ax[4] = {0.f, 0.f, 0.f, 0.f};
            float ay[4] = {0.f, 0.f, 0.f, 0.f};
            int lo = r0 - KR; if (lo < 0) lo = 0;
            int hi = r0 + KR; if (hi > H - 1) hi = H - 1;
            int k = 0;
            for (int j = lo; j <= hi; ++j, ++k) {
                float2 v = mb2[j * (W / 2) + c];
                ax[k & 3] += v.x; ay[k & 3] += v.y;
            }
            const float ix = (ax[0] + ax[1]) + (ax[2] + ax[3]);
            const float iy = (ay[0] + ay[1]) + (ay[2] + ay[3]);

            float addx = 0.f, addy = 0.f, subx = 0.f, suby = 0.f;
            #pragma unroll
            for (int rr = 0; rr < ROWS; ++rr) {
                const int r = r0 + rr;
                float vx = (ix + addx) - subx;
                float vy = (iy + addy) - suby;
                unsigned qx = (unsigned)__float2int_rn(vx * QS);
                unsigned qy = (unsigned)__float2int_rn(vy * QS);
                *(unsigned short*)&s_v[rr * VSTRIDE + 16 + 2 * c] =
                    (unsigned short)(qx | (qy << 8));
                int ar = r + KR + 1;
                int sr = r - KR;
                if (ar < H) {
                    float2 v = mb2[ar * (W / 2) + c];
                    addx += v.x; addy += v.y;
                }
                if (sr >= 0) {
                    float2 v = mb2[sr * (W / 2) + c];
                    subx += v.x; suby += v.y;
                }
            }
        }
    }
    __syncthreads();

    // ========== Phase B: dp4a horizontal box + elementwise ==================
    const int u = t & 63;               // thread within row (8 cols each)
    const int g = t >> 6;               // 0..3

    float a0 = 0.f, a1 = 0.f, a2 = 0.f, a3 = 0.f;

    #pragma unroll
    for (int pass = 0; pass < 2; ++pass) {
        const int lr = pass * 4 + g;    // local row 0..7
        const int r  = r0 + lr;

        // 5 aligned LDS.64 covering bytes 8u .. 8u+39 of the padded row
        const uint2* vrow = (const uint2*)&s_v[lr * VSTRIDE];
        uint2 L0 = vrow[u + 0];
        uint2 L1 = vrow[u + 1];
        uint2 L2 = vrow[u + 2];
        uint2 L3 = vrow[u + 3];
        uint2 L4 = vrow[u + 4];

        // streaming inputs: fp32 mask (L1/L2-hot from phase A) + pred (DRAM)
        const float4* mrow = (const float4*)(mb + (size_t)r * W);
        const float4* prow = (const float4*)(pb + (size_t)r * W);
        float4 m4a = mrow[u * 2 + 0];
        float4 m4b = mrow[u * 2 + 1];
        float4 p4a = __ldcg(&prow[u * 2 + 0]);
        float4 p4b = __ldcg(&prow[u * 2 + 1]);

        // integer prefix over 40 bytes via dp4a
        unsigned w0 = L0.x, w1 = L0.y, w8 = L4.x, w9 = L4.y;
        const unsigned M1 = 0x01010101u;
        unsigned wp1 = __dp4a(w0, M1, 0u);
        unsigned wp2 = __dp4a(w1, M1, wp1);
        unsigned wp3 = __dp4a(L1.x, M1, wp2);
        unsigned wp4 = __dp4a(L1.y, M1, wp3);
        unsigned wp5 = __dp4a(L2.x, M1, wp4);
        unsigned wp6 = __dp4a(L2.y, M1, wp5);
        unsigned wp7 = __dp4a(L3.x, M1, wp6);
        unsigned wp8 = __dp4a(L3.y, M1, wp7);
        unsigned wp9 = __dp4a(w8, M1, wp8);

        unsigned loS[8], hiS[8];
        loS[0] = __dp4a(w0, 0x00000001u, 0u);
        loS[1] = __dp4a(w0, 0x00000101u, 0u);
        loS[2] = __dp4a(w0, 0x00010101u, 0u);
        loS[3] = wp1;
        loS[4] = __dp4a(w1, 0x00000001u, wp1);
        loS[5] = __dp4a(w1, 0x00000101u, wp1);
        loS[6] = __dp4a(w1, 0x00010101u, wp1);
        loS[7] = wp2;
        hiS[0] = wp8;
        hiS[1] = __dp4a(w8, 0x00000001u, wp8);
        hiS[2] = __dp4a(w8, 0x00000101u, wp8);
        hiS[3] = __dp4a(w8, 0x00010101u, wp8);
        hiS[4] = wp9;
        hiS[5] = __dp4a(w9, 0x00000001u, wp9);
        hiS[6] = __dp4a(w9, 0x00000101u, wp9);
        hiS[7] = __dp4a(w9, 0x00010101u, wp9);

        float mv[8] = {m4a.x, m4a.y, m4a.z, m4a.w, m4b.x, m4b.y, m4b.z, m4b.w};
        float pv[8] = {p4a.x, p4a.y, p4a.z, p4a.w, p4b.x, p4b.y, p4b.z, p4b.w};

        #pragma unroll
        for (int i = 0; i < 8; ++i) {
            float box  = (float)(int)(hiS[i] - loS[i]) * BOXSCALE;
            float m    = mv[i];
            float p    = pv[i];
            float weit = 1.0f + MUF * fabsf(box - m);

            float eexp = __expf(-fabsf(p));
            float bce  = fmaxf(p, 0.0f) - p * m + __logf(1.0f + eexp);
            float rcp  = __fdividef(1.0f, 1.0f + eexp);
            float ps   = (p >= 0.0f) ? rcp : eexp * rcp;

            a0 += weit * bce;
            a1 += weit;
            float wps = weit * ps;
            a2 += wps * m;
            a3 += wps + weit * m;
        }
    }

    // ---- warp reduction ----
    const int wid  = t >> 5;
    const int lane = t & 31;
    #pragma unroll
    for (int d = 16; d > 0; d >>= 1) {
        a0 += __shfl_down_sync(0xffffffffu, a0, d);
        a1 += __shfl_down_sync(0xffffffffu, a1, d);
        a2 += __shfl_down_sync(0xffffffffu, a2, d);
        a3 += __shfl_down_sync(0xffffffffu, a3, d);
    }
    if (lane == 0) {
        red[wid * 4 + 0] = a0;
        red[wid * 4 + 1] = a1;
        red[wid * 4 + 2] = a2;
        red[wid * 4 + 3] = a3;
    }
    __syncthreads();

    // ---- cross-warp reduction in warp 0 (shuffle tree) ----
    if (wid == 0) {
        float y = red[lane];                 // lane = w*4 + k, w<8, k<4
        y += __shfl_xor_sync(0xffffffffu, y, 4);
        y += __shfl_xor_sync(0xffffffffu, y, 8);
        y += __shfl_xor_sync(0xffffffffu, y, 16);
        float s0 = __shfl_sync(0xffffffffu, y, 0);
        float s1 = __shfl_sync(0xffffffffu, y, 1);
        float s2 = __shfl_sync(0xffffffffu, y, 2);
        float s3 = __shfl_sync(0xffffffffu, y, 3);
        if (lane == 0) {
            __stcg(&g_part4[blockIdx.x], make_float4(s0, s1, s2, s3));
            unsigned int old;
            asm volatile("atom.acq_rel.gpu.global.add.u32 %0, [%1], %2;"
                         : "=r"(old) : "l"(&g_count), "r"(1u) : "memory");
            flag = (old == NBLK - 1) ? 1.f : 0.f;
        }
    }
    __syncthreads();

    // ---------- last block finalizes ----------
    if (flag != 0.f) {
        if (t < 128) {
            const int bb = t >> 3;           // batch 0..15
            const int j  = t & 7;            // chunk 0..7 (8 blocks each)
            float s0 = 0.f, s1 = 0.f, s2 = 0.f, s3 = 0.f;
            const float4* gp = g_part4 + bb * (NBLK / NB) + j * 8;
            #pragma unroll
            for (int kk = 0; kk < 8; ++kk) {
                float4 vv = __ldcg(&gp[kk]);
                s0 += vv.x; s1 += vv.y; s2 += vv.z; s3 += vv.w;
            }
            #pragma unroll
            for (int d = 4; d > 0; d >>= 1) {
                s0 += __shfl_down_sync(0xffffffffu, s0, d, 8);
                s1 += __shfl_down_sync(0xffffffffu, s1, d, 8);
                s2 += __shfl_down_sync(0xffffffffu, s2, d, 8);
                s3 += __shfl_down_sync(0xffffffffu, s3, d, 8);
            }
            if (j == 0) {
                float wbce = s0 / s1;
                float wiou = 1.0f - (s2 + 1.0f) / (s3 - s2 + 1.0f);
                red[bb] = wbce + wiou;
            }
        }
        __syncthreads();
        if (t == 0) {
            float s = 0.f;
            #pragma unroll
            for (int kk = 0; kk < NB; ++kk) s += red[kk];
            out[0] = s * (1.0f / NB);
            g_count = 0;                     // self-reset for next graph replay
        }
    }
}

extern "C" void kernel_launch(void* const* d_in, const int* in_sizes, int n_in,
                              void* d_out, int out_size) {
    const float* pred = (const float*)d_in[0];
    const float* mask = (const float*)d_in[1];
    if (n_in >= 2 && in_sizes[0] == NB * H * W && in_sizes[1] == NB * 2 * H * W) {
        mask = (const float*)d_in[0];
        pred = (const float*)d_in[1];
    }
    float* out = (float*)d_out;

    fused_kernel<<<NBLK, 256>>>(pred, mask, out);
}